// round 15
// baseline (speedup 1.0000x reference)
#include <cuda_runtime.h>
#include <cuda_fp16.h>
#include <cstdint>

// out[b,n,e] = sum_m A[n,m] * (sum_d Z[b,m,d] * W[d,e])
// B=16, N=4096, D_IN=64, D_OUT=64
//   convA: A_h = fp16(A)                          [4096][4096] half, K-major
//   gemm1: Xt[c][m] = fp16(sum_d Z[b,m,d]*W[d,e]) [1024][4096] half, K-major (c=b*64+e)
//   gemm2: split-K makespan-balanced workers (one continuous pipeline per worker)
//          -> partials; reduce: out = p0 + p1
//
// 128 output tiles (32 bm x 4 bn) x 64 k-chunks = 8192 units.
// Worker w in [0,147) owns units [56w, min(56w+56, 8192)).
// Every tile window [64t, 64t+64) has exactly 2 contributing runs:
//   - the run covering the window start (u0 <= 64t)      -> slot 0
//   - the unique run starting strictly inside             -> slot 1
// (56k mod 64 is a multiple of 8, so two strict-interior starts would need a
//  gap < 8 -- impossible; and a run is 56 < 64 units so it never covers a
//  whole window alone.)  2-way fp32 add in reduce is order-independent.

#define NCOLSX 1024
#define KDIM  4096

__device__ __align__(1024) __half g_Ah[4096 * KDIM];       // fp16 A (32 MB)
__device__ __align__(1024) __half g_Xt[NCOLSX * KDIM];     // fp16 (Z@W)^T (8 MB)
__device__ __align__(1024) float  g_part[2 * 128 * 32768]; // partials (33.5 MB)

// ---------------- helpers ----------------
__device__ __forceinline__ uint32_t smem_u32(const void* p) {
    return (uint32_t)__cvta_generic_to_shared(p);
}
__device__ __forceinline__ void cp_async16_s(uint32_t dst_smem, const void* src) {
    asm volatile("cp.async.cg.shared.global [%0], [%1], 16;\n"
                 :: "r"(dst_smem), "l"(src) : "memory");
}
__device__ __forceinline__ void cp_commit() {
    asm volatile("cp.async.commit_group;\n" ::: "memory");
}
__device__ __forceinline__ void ldsm_x4(uint32_t& r0, uint32_t& r1, uint32_t& r2, uint32_t& r3,
                                        uint32_t addr) {
    asm volatile("ldmatrix.sync.aligned.m8n8.x4.shared.b16 {%0,%1,%2,%3}, [%4];\n"
                 : "=r"(r0), "=r"(r1), "=r"(r2), "=r"(r3) : "r"(addr) : "memory");
}

// ---------------- kernel 0: A -> fp16 (4 independent float4 per thread) ----------------
__global__ void __launch_bounds__(256) convA_kernel(const float4* __restrict__ A) {
    int i = blockIdx.x * 256 + threadIdx.x;   // 4096 blocks; 4 chunks of 1,048,576 float4
    float4 v[4];
    #pragma unroll
    for (int r = 0; r < 4; r++) v[r] = __ldcs(A + i + r * 1048576);
    #pragma unroll
    for (int r = 0; r < 4; r++) {
        __half2 h0 = __floats2half2_rn(v[r].x, v[r].y);
        __half2 h1 = __floats2half2_rn(v[r].z, v[r].w);
        uint2 o;
        o.x = *reinterpret_cast<uint32_t*>(&h0);
        o.y = *reinterpret_cast<uint32_t*>(&h1);
        reinterpret_cast<uint2*>(g_Ah)[i + r * 1048576] = o;
    }
}

// ---------------- kernel 1: Xt = fp16((Z @ W)^T) ----------------
__global__ void __launch_bounds__(256) gemm1_kernel(const float* __restrict__ Z,
                                                    const float* __restrict__ W) {
    __shared__ float Zs[64 * 65];
    __shared__ float Ws[64 * 64];
    const int tid = threadIdx.x;
    const int m0  = blockIdx.x * 64;
    const int b   = blockIdx.y;

    const float* Zg = Z + (size_t)((b << 12) + m0) * 64;
    #pragma unroll
    for (int r = 0; r < 4; r++) {
        int i = tid + r * 256;            // 1024 float4
        int row = i >> 4, c4 = (i & 15) * 4;
        float4 v = __ldg(reinterpret_cast<const float4*>(Zg + (size_t)row * 64 + c4));
        float* zp = Zs + row * 65 + c4;
        zp[0] = v.x; zp[1] = v.y; zp[2] = v.z; zp[3] = v.w;
    }
    #pragma unroll
    for (int r = 0; r < 4; r++) {
        int i = tid + r * 256;
        reinterpret_cast<float4*>(Ws)[i] = __ldg(reinterpret_cast<const float4*>(W) + i);
    }
    __syncthreads();

    const int ml = tid & 63;
    const int e0 = (tid >> 6) * 16;

    float acc[16];
    #pragma unroll
    for (int j = 0; j < 16; j++) acc[j] = 0.0f;

    #pragma unroll 4
    for (int d = 0; d < 64; d++) {
        float zv = Zs[ml * 65 + d];
        const float4* wp = reinterpret_cast<const float4*>(Ws + d * 64 + e0);
        #pragma unroll
        for (int q = 0; q < 4; q++) {
            float4 w = wp[q];
            acc[q * 4 + 0] = fmaf(zv, w.x, acc[q * 4 + 0]);
            acc[q * 4 + 1] = fmaf(zv, w.y, acc[q * 4 + 1]);
            acc[q * 4 + 2] = fmaf(zv, w.z, acc[q * 4 + 2]);
            acc[q * 4 + 3] = fmaf(zv, w.w, acc[q * 4 + 3]);
        }
    }

    #pragma unroll
    for (int j = 0; j < 16; j++) {
        g_Xt[(size_t)((b << 6) + e0 + j) * KDIM + m0 + ml] = __float2half_rn(acc[j]);
    }
}

// ---------------- kernel 2: split-K worker, one continuous pipeline ----------------
// Tile 128(M) x 256(N), 256 threads / 8 warps (2 along M x 4 along N), warp 64x64.
// BK=64 halves per k-chunk (128 B rows), 4 stages, single sync per chunk.
#define BM 128
#define BN 256
#define BK 64
#define PITCH 72                       // 64 + 8 pad halves -> conflict-free ldmatrix
#define A_TILE_H (BM * PITCH)          // 9216 halves
#define B_TILE_H (BN * PITCH)          // 18432 halves
#define STAGE_H  (A_TILE_H + B_TILE_H) // 27648 halves
#define SMEM_BYTES (4 * STAGE_H * 2)   // 221184
#define RUN 56
#define NUNITS 8192
#define NWORKERS 147

__global__ void __launch_bounds__(256, 1) gemm2_kernel() {
    extern __shared__ __half smem[];

    const int tid  = threadIdx.x;
    const int wid  = tid >> 5;
    const int lane = tid & 31;
    const int g    = lane >> 2;
    const int t4   = lane & 3;
    const int wm   = (wid & 1) * 64;
    const int wn   = (wid >> 1) * 64;

    const uint32_t S_u = smem_u32(smem);
    const int a_off = (wm + (lane & 15)) * PITCH + (lane >> 4) * 8;
    const int b_off = (wn + ((lane >> 4) << 3) + (lane & 7)) * PITCH + ((lane >> 3) & 1) * 8;

    const int u0    = RUN * blockIdx.x;
    const int total = min(u0 + RUN, NUNITS) - u0;

    // load unit u0+idx into stage s (addresses derived per unit)
    auto load_unit = [&](int idx, int s) {
        const int u = u0 + idx;
        const int t = u >> 6;
        const int c = u & 63;
        const uint32_t Sb = S_u + (s * STAGE_H) * 2;
        const __half* Ag = g_Ah + (size_t)(t >> 2) * (BM * KDIM) + (size_t)c * BK;
        #pragma unroll
        for (int r = 0; r < 4; r++) {
            int j   = tid + r * 256;
            int row = j >> 3;
            int cv  = (j & 7) * 8;
            cp_async16_s(Sb + (row * PITCH + cv) * 2, Ag + (size_t)row * KDIM + cv);
        }
        const __half* Bg = g_Xt + (size_t)(t & 3) * (BN * KDIM) + (size_t)c * BK;
        const uint32_t Bb = Sb + A_TILE_H * 2;
        #pragma unroll
        for (int r = 0; r < 8; r++) {
            int j   = tid + r * 256;
            int row = j >> 3;
            int cv  = (j & 7) * 8;
            cp_async16_s(Bb + (row * PITCH + cv) * 2, Bg + (size_t)row * KDIM + cv);
        }
    };

    float acc[4][8][4];
    #pragma unroll
    for (int a = 0; a < 4; a++)
        #pragma unroll
        for (int b = 0; b < 8; b++)
            #pragma unroll
            for (int c = 0; c < 4; c++) acc[a][b][c] = 0.0f;

    load_unit(0, 0); cp_commit();
    load_unit(1, 1); cp_commit();
    load_unit(2, 2); cp_commit();

    for (int i = 0; i < total; i++) {
        asm volatile("cp.async.wait_group 2;\n" ::: "memory");
        __syncthreads();   // all warps done reading stage (i+3)&3 (last read at iter i-1)

        int li = i + 3;
        if (li < total) load_unit(li, li & 3);
        cp_commit();

        const uint32_t Asc = S_u + ((i & 3) * STAGE_H) * 2;
        const uint32_t Bsc = Asc + A_TILE_H * 2;

        #pragma unroll
        for (int ks = 0; ks < 4; ks++) {
            const int kb = ks * 16;
            uint32_t af[4][4];
            uint32_t bf[8][2];
            #pragma unroll
            for (int tm = 0; tm < 4; tm++) {
                ldsm_x4(af[tm][0], af[tm][1], af[tm][2], af[tm][3],
                        Asc + (a_off + tm * 16 * PITCH + kb) * 2);
            }
            #pragma unroll
            for (int q = 0; q < 4; q++) {
                ldsm_x4(bf[2 * q][0], bf[2 * q][1], bf[2 * q + 1][0], bf[2 * q + 1][1],
                        Bsc + (b_off + q * 16 * PITCH + kb) * 2);
            }
            #pragma unroll
            for (int tm = 0; tm < 4; tm++) {
                #pragma unroll
                for (int tn = 0; tn < 8; tn++) {
                    asm volatile(
                        "mma.sync.aligned.m16n8k16.row.col.f32.f16.f16.f32 "
                        "{%0,%1,%2,%3}, {%4,%5,%6,%7}, {%8,%9}, {%0,%1,%2,%3};\n"
                        : "+f"(acc[tm][tn][0]), "+f"(acc[tm][tn][1]),
                          "+f"(acc[tm][tn][2]), "+f"(acc[tm][tn][3])
                        : "r"(af[tm][0]), "r"(af[tm][1]), "r"(af[tm][2]), "r"(af[tm][3]),
                          "r"(bf[tn][0]), "r"(bf[tn][1]));
                }
            }
        }

        // tile boundary or end of run: flush accumulators (register-only; no sync needed)
        const int u = u0 + i;
        if (i == total - 1 || (u & 63) == 63) {
            const int t    = u >> 6;
            const int slot = (u0 > (t << 6)) ? 1 : 0;
            float* P = g_part + ((size_t)slot * 128 + t) * 32768;
            #pragma unroll
            for (int tm = 0; tm < 4; tm++) {
                #pragma unroll
                for (int tn = 0; tn < 8; tn++) {
                    int ml = wm + tm * 16 + g;
                    int cl = wn + tn * 8 + t4 * 2;
                    *reinterpret_cast<float2*>(P + ml * 256 + cl) =
                        make_float2(acc[tm][tn][0], acc[tm][tn][1]);
                    *reinterpret_cast<float2*>(P + (ml + 8) * 256 + cl) =
                        make_float2(acc[tm][tn][2], acc[tm][tn][3]);
                    acc[tm][tn][0] = 0.0f; acc[tm][tn][1] = 0.0f;
                    acc[tm][tn][2] = 0.0f; acc[tm][tn][3] = 0.0f;
                }
            }
        }
    }
}

// ---------------- kernel 3: out = part0 + part1 (2 float4 per thread) ----------------
// out has 1,048,576 float4 -> grid 2048 x 256, 2 chunks of 524,288.
__global__ void __launch_bounds__(256) reduce_kernel(float4* __restrict__ out) {
    int j0 = blockIdx.x * 256 + threadIdx.x;
    float4 a[2], b[2];
    int idx[2];
    #pragma unroll
    for (int r = 0; r < 2; r++) {
        int j  = j0 + r * 524288;
        int e4 = j & 15;
        int rr = j >> 4;
        int bb = rr >> 12;
        int n  = rr & 4095;
        int c0 = bb * 64 + e4 * 4;
        int t  = ((n >> 7) << 2) + (c0 >> 8);
        int p  = t * 32768 + (n & 127) * 256 + (c0 & 255);
        idx[r] = j;
        a[r] = __ldg(reinterpret_cast<const float4*>(g_part + p));
        b[r] = __ldg(reinterpret_cast<const float4*>(g_part + 128 * 32768 + p));
    }
    #pragma unroll
    for (int r = 0; r < 2; r++) {
        out[idx[r]] = make_float4(a[r].x + b[r].x, a[r].y + b[r].y,
                                  a[r].z + b[r].z, a[r].w + b[r].w);
    }
}

// ---------------- launch ----------------
extern "C" void kernel_launch(void* const* d_in, const int* in_sizes, int n_in,
                              void* d_out, int out_size) {
    const float* Z = (const float*)d_in[0];   // [16, 4096, 64]
    const float* A = (const float*)d_in[1];   // [4096, 4096]
    const float* W = (const float*)d_in[2];   // [64, 64]
    float* out = (float*)d_out;               // [16, 4096, 64]
    (void)in_sizes; (void)n_in; (void)out_size;

    static cudaStream_t s2 = nullptr;
    static cudaEvent_t evF = nullptr, evJ = nullptr;
    if (!s2) {
        cudaStreamCreateWithFlags(&s2, cudaStreamNonBlocking);
        cudaEventCreateWithFlags(&evF, cudaEventDisableTiming);
        cudaEventCreateWithFlags(&evJ, cudaEventDisableTiming);
        cudaFuncSetAttribute(gemm2_kernel,
                             cudaFuncAttributeMaxDynamicSharedMemorySize, SMEM_BYTES);
    }

    // Fork gemm1 (independent of convA) onto the side stream; join before gemm2.
    cudaEventRecord(evF, 0);
    cudaStreamWaitEvent(s2, evF, 0);

    gemm1_kernel<<<dim3(64, 16), 256, 0, s2>>>(Z, W);
    cudaEventRecord(evJ, s2);

    convA_kernel<<<4096, 256>>>(reinterpret_cast<const float4*>(A));

    cudaStreamWaitEvent(0, evJ, 0);
    gemm2_kernel<<<NWORKERS, 256, SMEM_BYTES>>>();
    reduce_kernel<<<2048, 256>>>(reinterpret_cast<float4*>(out));
}

// round 16
// speedup vs baseline: 1.4987x; 1.4987x over previous
#include <cuda_runtime.h>
#include <cuda_fp16.h>
#include <cstdint>

// out[b,n,e] = sum_m A[n,m] * (sum_d Z[b,m,d] * W[d,e])
// B=16, N=4096, D_IN=64, D_OUT=64
//   convA: A_h = fp16(A)                          [4096][4096] half, K-major
//   gemm1: Xt[c][m] = fp16(sum_d Z[b,m,d]*W[d,e]) [1024][4096] half, K-major (c=b*64+e)
//   gemm2: split-K makespan-balanced workers (segmented, R12-proven) -> partials
//   reduce: out = p0 + p1
//
// 128 output tiles (32 bm x 4 bn) x 64 k-chunks = 8192 units.
// Worker w in [0,147) owns units [56w, min(56w+56, 8192)). Every tile window
// gets exactly 2 contributors: start-covering run -> slot0, unique strictly-
// interior starter -> slot1. 2-way fp32 add is order-independent.

#define NCOLSX 1024
#define KDIM  4096

__device__ __align__(1024) __half g_Ah[4096 * KDIM];       // fp16 A (32 MB)
__device__ __align__(1024) __half g_Xt[NCOLSX * KDIM];     // fp16 (Z@W)^T (8 MB)
__device__ __align__(1024) float  g_part[2 * 128 * 32768]; // partials (33.5 MB)

// ---------------- helpers ----------------
__device__ __forceinline__ uint32_t smem_u32(const void* p) {
    return (uint32_t)__cvta_generic_to_shared(p);
}
__device__ __forceinline__ void cp_async16_s(uint32_t dst_smem, const void* src) {
    asm volatile("cp.async.cg.shared.global [%0], [%1], 16;\n"
                 :: "r"(dst_smem), "l"(src) : "memory");
}
__device__ __forceinline__ void cp_commit() {
    asm volatile("cp.async.commit_group;\n" ::: "memory");
}
__device__ __forceinline__ void ldsm_x4(uint32_t& r0, uint32_t& r1, uint32_t& r2, uint32_t& r3,
                                        uint32_t addr) {
    asm volatile("ldmatrix.sync.aligned.m8n8.x4.shared.b16 {%0,%1,%2,%3}, [%4];\n"
                 : "=r"(r0), "=r"(r1), "=r"(r2), "=r"(r3) : "r"(addr) : "memory");
}

// ---------------- kernel 0: A -> fp16 (4 independent float4 per thread) ----------------
__global__ void __launch_bounds__(256) convA_kernel(const float4* __restrict__ A) {
    int i = blockIdx.x * 256 + threadIdx.x;   // 4096 blocks; 4 chunks of 1,048,576 float4
    float4 v[4];
    #pragma unroll
    for (int r = 0; r < 4; r++) v[r] = __ldcs(A + i + r * 1048576);
    #pragma unroll
    for (int r = 0; r < 4; r++) {
        __half2 h0 = __floats2half2_rn(v[r].x, v[r].y);
        __half2 h1 = __floats2half2_rn(v[r].z, v[r].w);
        uint2 o;
        o.x = *reinterpret_cast<uint32_t*>(&h0);
        o.y = *reinterpret_cast<uint32_t*>(&h1);
        reinterpret_cast<uint2*>(g_Ah)[i + r * 1048576] = o;
    }
}

// ---------------- kernel 1: Xt = fp16((Z @ W)^T) ----------------
__global__ void __launch_bounds__(256) gemm1_kernel(const float* __restrict__ Z,
                                                    const float* __restrict__ W) {
    __shared__ float Zs[64 * 65];
    __shared__ float Ws[64 * 64];
    const int tid = threadIdx.x;
    const int m0  = blockIdx.x * 64;
    const int b   = blockIdx.y;

    const float* Zg = Z + (size_t)((b << 12) + m0) * 64;
    #pragma unroll
    for (int r = 0; r < 4; r++) {
        int i = tid + r * 256;            // 1024 float4
        int row = i >> 4, c4 = (i & 15) * 4;
        float4 v = __ldg(reinterpret_cast<const float4*>(Zg + (size_t)row * 64 + c4));
        float* zp = Zs + row * 65 + c4;
        zp[0] = v.x; zp[1] = v.y; zp[2] = v.z; zp[3] = v.w;
    }
    #pragma unroll
    for (int r = 0; r < 4; r++) {
        int i = tid + r * 256;
        reinterpret_cast<float4*>(Ws)[i] = __ldg(reinterpret_cast<const float4*>(W) + i);
    }
    __syncthreads();

    const int ml = tid & 63;
    const int e0 = (tid >> 6) * 16;

    float acc[16];
    #pragma unroll
    for (int j = 0; j < 16; j++) acc[j] = 0.0f;

    #pragma unroll 4
    for (int d = 0; d < 64; d++) {
        float zv = Zs[ml * 65 + d];
        const float4* wp = reinterpret_cast<const float4*>(Ws + d * 64 + e0);
        #pragma unroll
        for (int q = 0; q < 4; q++) {
            float4 w = wp[q];
            acc[q * 4 + 0] = fmaf(zv, w.x, acc[q * 4 + 0]);
            acc[q * 4 + 1] = fmaf(zv, w.y, acc[q * 4 + 1]);
            acc[q * 4 + 2] = fmaf(zv, w.z, acc[q * 4 + 2]);
            acc[q * 4 + 3] = fmaf(zv, w.w, acc[q * 4 + 3]);
        }
    }

    #pragma unroll
    for (int j = 0; j < 16; j++) {
        g_Xt[(size_t)((b << 6) + e0 + j) * KDIM + m0 + ml] = __float2half_rn(acc[j]);
    }
}

// ---------------- kernel 2: split-K worker (segmented; R12-proven) ----------------
// Tile 128(M) x 256(N), 256 threads / 8 warps (2 along M x 4 along N), warp 64x64.
// BK=64 halves per k-chunk (128 B rows), 4 stages, single sync per chunk.
#define BM 128
#define BN 256
#define BK 64
#define PITCH 72                       // 64 + 8 pad halves -> conflict-free ldmatrix
#define A_TILE_H (BM * PITCH)          // 9216 halves
#define B_TILE_H (BN * PITCH)          // 18432 halves
#define STAGE_H  (A_TILE_H + B_TILE_H) // 27648 halves
#define SMEM_BYTES (4 * STAGE_H * 2)   // 221184
#define RUN 56
#define NUNITS 8192
#define NWORKERS 147

__global__ void __launch_bounds__(256, 1) gemm2_kernel() {
    extern __shared__ __half smem[];

    const int tid  = threadIdx.x;
    const int wid  = tid >> 5;
    const int lane = tid & 31;
    const int g    = lane >> 2;
    const int t4   = lane & 3;
    const int wm   = (wid & 1) * 64;
    const int wn   = (wid >> 1) * 64;

    const uint32_t S_u = smem_u32(smem);
    const int a_off = (wm + (lane & 15)) * PITCH + (lane >> 4) * 8;
    const int b_off = (wn + ((lane >> 4) << 3) + (lane & 7)) * PITCH + ((lane >> 3) & 1) * 8;

    const int u0 = RUN * blockIdx.x;
    const int u1 = min(u0 + RUN, NUNITS);

    int u = u0;
    while (u < u1) {
        const int t   = u >> 6;                 // tile id
        const int c0  = u & 63;                 // first chunk in tile
        const int len = min(64 - c0, u1 - u);   // >= 8 always
        const int slot = (u0 > (t << 6)) ? 1 : 0;
        const int bm = t >> 2;
        const int bn = t & 3;

        const __half* Ag0 = g_Ah + (size_t)(bm * BM) * KDIM + (size_t)c0 * BK;
        const __half* Bg0 = g_Xt + (size_t)(bn * BN) * KDIM + (size_t)c0 * BK;

        auto load_tile = [&](int i, int s) {
            const uint32_t Sb = S_u + (s * STAGE_H) * 2;
            const __half* Ag = Ag0 + i * BK;
            #pragma unroll
            for (int r = 0; r < 4; r++) {
                int j   = tid + r * 256;
                int row = j >> 3;
                int cv  = (j & 7) * 8;
                cp_async16_s(Sb + (row * PITCH + cv) * 2, Ag + (size_t)row * KDIM + cv);
            }
            const __half* Bg = Bg0 + i * BK;
            const uint32_t Bb = Sb + A_TILE_H * 2;
            #pragma unroll
            for (int r = 0; r < 8; r++) {
                int j   = tid + r * 256;
                int row = j >> 3;
                int cv  = (j & 7) * 8;
                cp_async16_s(Bb + (row * PITCH + cv) * 2, Bg + (size_t)row * KDIM + cv);
            }
        };

        float acc[4][8][4];
        #pragma unroll
        for (int a = 0; a < 4; a++)
            #pragma unroll
            for (int b = 0; b < 8; b++)
                #pragma unroll
                for (int c = 0; c < 4; c++) acc[a][b][c] = 0.0f;

        load_tile(0, 0); cp_commit();
        load_tile(1, 1); cp_commit();
        load_tile(2, 2); cp_commit();

        for (int i = 0; i < len; i++) {
            asm volatile("cp.async.wait_group 2;\n" ::: "memory");
            __syncthreads();

            int li = i + 3;
            if (li < len) load_tile(li, li & 3);
            cp_commit();

            const uint32_t Asc = S_u + ((i & 3) * STAGE_H) * 2;
            const uint32_t Bsc = Asc + A_TILE_H * 2;

            #pragma unroll
            for (int ks = 0; ks < 4; ks++) {
                const int kb = ks * 16;
                uint32_t af[4][4];
                uint32_t bf[8][2];
                #pragma unroll
                for (int tm = 0; tm < 4; tm++) {
                    ldsm_x4(af[tm][0], af[tm][1], af[tm][2], af[tm][3],
                            Asc + (a_off + tm * 16 * PITCH + kb) * 2);
                }
                #pragma unroll
                for (int q = 0; q < 4; q++) {
                    ldsm_x4(bf[2 * q][0], bf[2 * q][1], bf[2 * q + 1][0], bf[2 * q + 1][1],
                            Bsc + (b_off + q * 16 * PITCH + kb) * 2);
                }
                #pragma unroll
                for (int tm = 0; tm < 4; tm++) {
                    #pragma unroll
                    for (int tn = 0; tn < 8; tn++) {
                        asm volatile(
                            "mma.sync.aligned.m16n8k16.row.col.f32.f16.f16.f32 "
                            "{%0,%1,%2,%3}, {%4,%5,%6,%7}, {%8,%9}, {%0,%1,%2,%3};\n"
                            : "+f"(acc[tm][tn][0]), "+f"(acc[tm][tn][1]),
                              "+f"(acc[tm][tn][2]), "+f"(acc[tm][tn][3])
                            : "r"(af[tm][0]), "r"(af[tm][1]), "r"(af[tm][2]), "r"(af[tm][3]),
                              "r"(bf[tn][0]), "r"(bf[tn][1]));
                    }
                }
            }
        }
        __syncthreads();   // all warps done with smem before next segment's prologue

        // partial epilogue -> g_part[slot][t][m_local][n_local]
        float* P = g_part + ((size_t)slot * 128 + t) * 32768;
        #pragma unroll
        for (int tm = 0; tm < 4; tm++) {
            #pragma unroll
            for (int tn = 0; tn < 8; tn++) {
                int ml = wm + tm * 16 + g;
                int cl = wn + tn * 8 + t4 * 2;
                *reinterpret_cast<float2*>(P + ml * 256 + cl) =
                    make_float2(acc[tm][tn][0], acc[tm][tn][1]);
                *reinterpret_cast<float2*>(P + (ml + 8) * 256 + cl) =
                    make_float2(acc[tm][tn][2], acc[tm][tn][3]);
            }
        }

        u += len;
    }
}

// ---------------- kernel 3: out = part0 + part1 ----------------
// out has 16*4096*64 = 4,194,304 floats = 1,048,576 float4 -> grid 4096 x 256.
__global__ void __launch_bounds__(256) reduce_kernel(float4* __restrict__ out) {
    int j  = blockIdx.x * 256 + threadIdx.x;   // float4 id, 1,048,576 total
    int e4 = j & 15;                           // 16 float4 per 64-e row
    int r  = j >> 4;                           // bb*4096 + n   (65,536 rows)
    int bb = r >> 12;
    int n  = r & 4095;
    int c0 = bb * 64 + e4 * 4;                 // column id in [0,1024)
    int t  = ((n >> 7) << 2) + (c0 >> 8);      // tile id
    int p  = t * 32768 + (n & 127) * 256 + (c0 & 255);
    float4 a = __ldg(reinterpret_cast<const float4*>(g_part + p));
    float4 b = __ldg(reinterpret_cast<const float4*>(g_part + 128 * 32768 + p));
    out[j] = make_float4(a.x + b.x, a.y + b.y, a.z + b.z, a.w + b.w);
}

// ---------------- launch ----------------
extern "C" void kernel_launch(void* const* d_in, const int* in_sizes, int n_in,
                              void* d_out, int out_size) {
    const float* Z = (const float*)d_in[0];   // [16, 4096, 64]
    const float* A = (const float*)d_in[1];   // [4096, 4096]
    const float* W = (const float*)d_in[2];   // [64, 64]
    float* out = (float*)d_out;               // [16, 4096, 64]
    (void)in_sizes; (void)n_in; (void)out_size;

    static cudaStream_t s2 = nullptr;
    static cudaEvent_t evF = nullptr, evJ = nullptr;
    if (!s2) {
        cudaStreamCreateWithFlags(&s2, cudaStreamNonBlocking);
        cudaEventCreateWithFlags(&evF, cudaEventDisableTiming);
        cudaEventCreateWithFlags(&evJ, cudaEventDisableTiming);
        cudaFuncSetAttribute(gemm2_kernel,
                             cudaFuncAttributeMaxDynamicSharedMemorySize, SMEM_BYTES);
    }

    // Fork gemm1 (independent of convA) onto the side stream; join before gemm2.
    cudaEventRecord(evF, 0);
    cudaStreamWaitEvent(s2, evF, 0);

    gemm1_kernel<<<dim3(64, 16), 256, 0, s2>>>(Z, W);
    cudaEventRecord(evJ, s2);

    convA_kernel<<<4096, 256>>>(reinterpret_cast<const float4*>(A));

    cudaStreamWaitEvent(0, evJ, 0);
    gemm2_kernel<<<NWORKERS, 256, SMEM_BYTES>>>();
    reduce_kernel<<<4096, 256>>>(reinterpret_cast<float4*>(out));
}